// round 4
// baseline (speedup 1.0000x reference)
#include <cuda_runtime.h>
#include <math.h>
#include <stdint.h>

#define S_ 64
#define C_ 256
#define NN_ 4096
#define B_ 16
#define M_ 128
#define P_ 2080
#define TINV 10.0f
#define NEGIOU 0.5f
#define PTILES 17
#define TP 128
#define CK 16
#define CZ 2
#define KC (C_/CZ)          // 128 channels per z-slice
#define CHUNKS (KC/CK)      // 8
#define QBLOCKS (B_*PTILES) // 272

// scratch (device globals; no allocation allowed)
__device__ int   g_midx[P_];
__device__ int   g_b2s[B_];
__device__ int   g_m2s[M_];
__device__ int   g_s2b[S_];
__device__ float g_sfn[S_*C_];
__device__ float g_pl[M_];
__device__ float g_lossv[M_];
__device__ float g_qpart[QBLOCKS*S_];
__device__ float g_dots[(size_t)CZ*B_*PTILES*8192];   // partial dot tiles
__device__ float g_norms[CZ*B_*PTILES*TP];            // partial |v|^2 per p

// ---------------------------------------------------------------------------
// cp.async helpers
// ---------------------------------------------------------------------------
__device__ __forceinline__ void cpa4(void* dst_smem, const void* src_gmem) {
    uint32_t d = (uint32_t)__cvta_generic_to_shared(dst_smem);
    asm volatile("cp.async.ca.shared.global [%0], [%1], 4;" :: "r"(d), "l"(src_gmem));
}
__device__ __forceinline__ void cpa_commit() {
    asm volatile("cp.async.commit_group;");
}
__device__ __forceinline__ void cpa_wait1() {
    asm volatile("cp.async.wait_group 1;");
}
__device__ __forceinline__ void cpa_wait0() {
    asm volatile("cp.async.wait_group 0;");
}

// ---------------------------------------------------------------------------
// Kernel 1: sentence-feature normalize (64 blocks x 256) + fused setup (blk 0)
// mask2d is static config: triu(64x64), P=2080, generated analytically.
// ---------------------------------------------------------------------------
__global__ void sfnorm_setup_kernel(const float* __restrict__ sf,
                                    const int* __restrict__ nsent,
                                    const int* __restrict__ ntarg) {
    int s = blockIdx.x;
    int t = threadIdx.x; // == c

    if (s == 0) {
        if (t < 64) {
            int off = t * 64 - (t * (t - 1)) / 2;
            for (int c = t; c < 64; c++)
                g_midx[off + (c - t)] = t * 64 + c;
        }
        if (t == 0) {
            int acc = 0;
            for (int b = 0; b < B_; b++) {
                g_b2s[b] = acc;
                for (int j = 0; j < nsent[b]; j++)
                    if (acc + j < S_) g_s2b[acc + j] = b;
                acc += nsent[b];
            }
            int mi = 0;
            for (int ss = 0; ss < S_; ss++)
                for (int j = 0; j < ntarg[ss]; j++)
                    if (mi < M_) g_m2s[mi++] = ss;
        }
    }

    float v = sf[s * C_ + t];
    float x = v * v;
#pragma unroll
    for (int o = 16; o; o >>= 1) x += __shfl_down_sync(0xffffffffu, x, o);
    __shared__ float red[8];
    if ((t & 31) == 0) red[t >> 5] = x;
    __syncthreads();
    if (t == 0) {
        float acc = 0.f;
#pragma unroll
        for (int i = 0; i < 8; i++) acc += red[i];
        red[0] = acc;
    }
    __syncthreads();
    float n = fmaxf(sqrtf(red[0]), 1e-12f);
    g_sfn[s * C_ + t] = v / n;
}

// ---------------------------------------------------------------------------
// Kernel 2: per-moment top-1 proposal + inter-video loss (128 blocks x 256)
// ---------------------------------------------------------------------------
__global__ void video_kernel(const float* __restrict__ video,
                             const float* __restrict__ iou2ds) {
    int m = blockIdx.x;
    int t = threadIdx.x;
    int sm = g_m2s[m];

    // argmax over P of iou2ds[m, midx[p]] (tie -> lowest p)
    float best = -1e30f;
    int bi = 0;
    for (int p = t; p < P_; p += 256) {
        float v = iou2ds[m * NN_ + g_midx[p]];
        if (v > best) { best = v; bi = p; }
    }
    __shared__ float sv[256];
    __shared__ int   sidx[256];
    sv[t] = best; sidx[t] = bi;
    __syncthreads();
    for (int o = 128; o; o >>= 1) {
        if (t < o) {
            float vo = sv[t + o]; int io = sidx[t + o];
            if (vo > sv[t] || (vo == sv[t] && io < sidx[t])) { sv[t] = vo; sidx[t] = io; }
        }
        __syncthreads();
    }
    int pflat = g_midx[sidx[0]];
    __syncthreads();

    // load v[c], normalize
    float vc = video[((size_t)sm * C_ + t) * NN_ + pflat];
    float x = vc * vc;
#pragma unroll
    for (int o = 16; o; o >>= 1) x += __shfl_down_sync(0xffffffffu, x, o);
    __shared__ float red[8];
    if ((t & 31) == 0) red[t >> 5] = x;
    __syncthreads();
    if (t == 0) {
        float acc = 0.f;
#pragma unroll
        for (int i = 0; i < 8; i++) acc += red[i];
        red[0] = acc;
    }
    __syncthreads();
    float nrm = fmaxf(sqrtf(red[0]), 1e-12f);
    sv[t] = vc / nrm;
    __syncthreads();

    // dots against all 64 normalized sentence vectors
    __shared__ float alls[S_];
    int w = t >> 5, l = t & 31;
#pragma unroll
    for (int k = 0; k < 8; k++) {
        int s = w * 8 + k;
        float acc = 0.f;
#pragma unroll
        for (int c = l; c < C_; c += 32) acc += sv[c] * g_sfn[s * C_ + c];
#pragma unroll
        for (int o = 16; o; o >>= 1) acc += __shfl_down_sync(0xffffffffu, acc, o);
        if (l == 0) alls[s] = acc;
    }
    __syncthreads();
    if (t == 0) {
        float pl = alls[sm] * TINV;
        float neg = 0.f;
        for (int s = 0; s < S_; s++)
            if (s != sm) neg += expf(alls[s] * TINV);
        g_pl[m] = pl;
        g_lossv[m] = logf(expf(pl) + neg) - pl;
    }
}

// ---------------------------------------------------------------------------
// Kernel 3: inter-query partial GEMM, C-split across blockIdx.z (CZ=2)
// grid (PTILES, B, CZ), 128 threads; 64s x 128p tile, 8x8 micro-tile
// thread layout: pi = tid&15 (p = pi*8+j), si = tid>>4 (s = si*8+a)
// cp.async double-buffered K pipeline (CK=16 per stage, 8 stages)
// ---------------------------------------------------------------------------
__global__ __launch_bounds__(128, 4) void query_kernel(const float* __restrict__ video) {
    int pt = blockIdx.x;
    int b  = blockIdx.y;
    int z  = blockIdx.z;
    int sb = g_b2s[b];
    int tid = threadIdx.x;
    int pi = tid & 15;
    int si = tid >> 4;

    __shared__ float sfc[2][CK * S_];   // [stage][cc*64+s]  8KB
    __shared__ float vt[2][CK][TP];     // [stage][cc][p]   16KB

    int ptbase = pt * TP;
    int pcol = ptbase + tid;
    int fidx = g_midx[pcol < P_ ? pcol : (P_ - 1)];
    const float* vbase = video + (size_t)sb * C_ * NN_ + (size_t)z * KC * NN_;

    float acc[8][8];
    float accn[8];
#pragma unroll
    for (int a = 0; a < 8; a++)
#pragma unroll
        for (int j = 0; j < 8; j++) acc[a][j] = 0.f;
#pragma unroll
    for (int j = 0; j < 8; j++) accn[j] = 0.f;

    int cbase = z * KC;

    // stage loader
    auto load_stage = [&](int chunk, int st) {
        int cb = chunk * CK;
#pragma unroll
        for (int i = 0; i < CK; i++)
            cpa4(&vt[st][i][tid], vbase + (size_t)(cb + i) * NN_ + fidx);
#pragma unroll
        for (int k = 0; k < (CK * S_) / 128; k++) {
            int idx = tid + k * 128;
            int i = idx >> 6, s = idx & 63;
            cpa4(&sfc[st][idx], &g_sfn[s * C_ + cbase + cb + i]);
        }
        cpa_commit();
    };

    load_stage(0, 0);
    load_stage(1, 1);

    for (int k = 0; k < CHUNKS; k++) {
        if (k < CHUNKS - 1) cpa_wait1(); else cpa_wait0();
        __syncthreads();
        int st = k & 1;
#pragma unroll
        for (int i = 0; i < CK; i++) {
            float4 v0 = *(const float4*)&vt[st][i][pi * 8];
            float4 v1 = *(const float4*)&vt[st][i][pi * 8 + 4];
            float4 s0 = *(const float4*)&sfc[st][i * 64 + si * 8];
            float4 s1 = *(const float4*)&sfc[st][i * 64 + si * 8 + 4];
            float vv[8] = {v0.x, v0.y, v0.z, v0.w, v1.x, v1.y, v1.z, v1.w};
            float ss[8] = {s0.x, s0.y, s0.z, s0.w, s1.x, s1.y, s1.z, s1.w};
#pragma unroll
            for (int j = 0; j < 8; j++) accn[j] = fmaf(vv[j], vv[j], accn[j]);
#pragma unroll
            for (int a = 0; a < 8; a++)
#pragma unroll
                for (int j = 0; j < 8; j++)
                    acc[a][j] = fmaf(ss[a], vv[j], acc[a][j]);
        }
        __syncthreads();
        if (k + 2 < CHUNKS) load_stage(k + 2, st);
    }

    // write partials (coalesced: each thread 64 consecutive floats)
    size_t bi = ((size_t)z * B_ + b) * PTILES + pt;
    float4* dst = (float4*)(g_dots + bi * 8192 + (size_t)tid * 64);
#pragma unroll
    for (int a = 0; a < 8; a++) {
        dst[a * 2]     = make_float4(acc[a][0], acc[a][1], acc[a][2], acc[a][3]);
        dst[a * 2 + 1] = make_float4(acc[a][4], acc[a][5], acc[a][6], acc[a][7]);
    }
    if (si == 0) {
#pragma unroll
        for (int j = 0; j < 8; j++)
            g_norms[bi * TP + pi * 8 + j] = accn[j];
    }
}

// ---------------------------------------------------------------------------
// Kernel 4: combine z-partials + masked exp-sum epilogue
// grid (PTILES, B), 128 threads; same thread layout as query_kernel
// ---------------------------------------------------------------------------
__global__ __launch_bounds__(128) void qepi_kernel(const float* __restrict__ iou2d) {
    int pt = blockIdx.x;
    int b  = blockIdx.y;
    int tid = threadIdx.x;
    int pi = tid & 15;
    int si = tid >> 4;
    int ptbase = pt * TP;

    size_t bi0 = ((size_t)b) * PTILES + pt;
    size_t bi1 = ((size_t)B_ + b) * PTILES + pt;
    const float4* d0 = (const float4*)(g_dots + bi0 * 8192 + (size_t)tid * 64);
    const float4* d1 = (const float4*)(g_dots + bi1 * 8192 + (size_t)tid * 64);

    float acc[8][8];
#pragma unroll
    for (int a = 0; a < 8; a++) {
        float4 x0 = d0[a * 2],     y0 = d1[a * 2];
        float4 x1 = d0[a * 2 + 1], y1 = d1[a * 2 + 1];
        acc[a][0] = x0.x + y0.x; acc[a][1] = x0.y + y0.y;
        acc[a][2] = x0.z + y0.z; acc[a][3] = x0.w + y0.w;
        acc[a][4] = x1.x + y1.x; acc[a][5] = x1.y + y1.y;
        acc[a][6] = x1.z + y1.z; acc[a][7] = x1.w + y1.w;
    }
    float inv[8];
#pragma unroll
    for (int j = 0; j < 8; j++) {
        float n = g_norms[bi0 * TP + pi * 8 + j] + g_norms[bi1 * TP + pi * 8 + j];
        inv[j] = TINV / fmaxf(sqrtf(n), 1e-12f);
    }

    __shared__ float part[S_][16];
#pragma unroll
    for (int a = 0; a < 8; a++) {
        int s = si * 8 + a;
        bool samevid = (g_s2b[s] == b);
        float sum = 0.f;
#pragma unroll
        for (int j = 0; j < 8; j++) {
            int p = ptbase + pi * 8 + j;
            if (p < P_) {
                bool excl = false;
                if (samevid) {
                    float io = iou2d[s * NN_ + g_midx[p]];
                    excl = (io > NEGIOU);
                }
                if (!excl) sum += __expf(acc[a][j] * inv[j]);
            }
        }
        part[s][pi] = sum;
    }
    __syncthreads();
    if (tid < S_) {
        float tot = 0.f;
#pragma unroll
        for (int k = 0; k < 16; k++) tot += part[tid][k];
        g_qpart[(b * PTILES + pt) * S_ + tid] = tot;
    }
}

// ---------------------------------------------------------------------------
// Kernel 5: fused qreduce + per-moment losses -> mean  (1 block x 128)
// ---------------------------------------------------------------------------
__global__ void final_kernel(float* __restrict__ out) {
    int t = threadIdx.x;
    __shared__ float qn[2][S_];
    // deterministic two-way split reduce of 272 partials per sentence
    {
        int s = t & 63;
        int h = t >> 6;       // 0 or 1
        float acc = 0.f;
        for (int i = h * 136; i < (h + 1) * 136; i++)
            acc += g_qpart[i * S_ + s];
        qn[h][s] = acc;
    }
    __syncthreads();

    int sm = g_m2s[t];
    float pl = g_pl[t];
    float qneg = qn[0][sm] + qn[1][sm];
    float lq = logf(expf(pl) + qneg) - pl;
    float v = g_lossv[t] + lq;
#pragma unroll
    for (int o = 16; o; o >>= 1) v += __shfl_down_sync(0xffffffffu, v, o);
    __shared__ float red[4];
    if ((t & 31) == 0) red[t >> 5] = v;
    __syncthreads();
    if (t == 0)
        out[0] = (red[0] + red[1] + red[2] + red[3]) / (float)M_;
}

// ---------------------------------------------------------------------------
extern "C" void kernel_launch(void* const* d_in, const int* in_sizes, int n_in,
                              void* d_out, int out_size) {
    const float* video = (const float*)d_in[0];         // (S,C,N,N)
    const float* sents = (const float*)d_in[1];         // (S,C)
    const float* iou2d = (const float*)d_in[2];         // (S,N,N)
    const float* iou2ds = (const float*)d_in[3];        // (M,N,N)
    const int* nsent = (const int*)d_in[4];             // (B,)
    const int* ntarg = (const int*)d_in[5];             // (S,)
    float* out = (float*)d_out;

    sfnorm_setup_kernel<<<S_, 256>>>(sents, nsent, ntarg);
    video_kernel<<<M_, 256>>>(video, iou2ds);
    query_kernel<<<dim3(PTILES, B_, CZ), 128>>>(video);
    qepi_kernel<<<dim3(PTILES, B_), 128>>>(iou2d);
    final_kernel<<<1, M_>>>(out);
}

// round 5
// speedup vs baseline: 1.0186x; 1.0186x over previous
#include <cuda_runtime.h>
#include <math.h>
#include <stdint.h>

#define S_ 64
#define C_ 256
#define NN_ 4096
#define B_ 16
#define M_ 128
#define P_ 2080
#define TINV 10.0f
#define NEGIOU 0.5f
#define PTILES 17
#define TP 128
#define CK 16
#define CHUNKS (C_/CK)      // 16
#define QBLOCKS (B_*PTILES) // 272

// scratch (device globals; no allocation allowed)
__device__ int   g_midx[P_];
__device__ int   g_b2s[B_];
__device__ int   g_m2s[M_];
__device__ int   g_s2b[S_];
__device__ float g_sfn[S_*C_];
__device__ float g_pl[M_];
__device__ float g_lossv[M_];
__device__ float g_qpart[QBLOCKS*S_];

// ---------------------------------------------------------------------------
// cp.async helpers
// ---------------------------------------------------------------------------
__device__ __forceinline__ void cpa4(void* dst_smem, const void* src_gmem) {
    uint32_t d = (uint32_t)__cvta_generic_to_shared(dst_smem);
    asm volatile("cp.async.ca.shared.global [%0], [%1], 4;" :: "r"(d), "l"(src_gmem));
}
__device__ __forceinline__ void cpa_commit() { asm volatile("cp.async.commit_group;"); }
__device__ __forceinline__ void cpa_wait1()  { asm volatile("cp.async.wait_group 1;"); }
__device__ __forceinline__ void cpa_wait0()  { asm volatile("cp.async.wait_group 0;"); }

// ---------------------------------------------------------------------------
// Kernel 1: sentence-feature normalize (64 blocks x 256) + fused setup (blk 0)
// mask2d is static config: triu(64x64), P=2080, generated analytically.
// ---------------------------------------------------------------------------
__global__ void sfnorm_setup_kernel(const float* __restrict__ sf,
                                    const int* __restrict__ nsent,
                                    const int* __restrict__ ntarg) {
    int s = blockIdx.x;
    int t = threadIdx.x; // == c

    if (s == 0) {
        if (t < 64) {
            int off = t * 64 - (t * (t - 1)) / 2;
            for (int c = t; c < 64; c++)
                g_midx[off + (c - t)] = t * 64 + c;
        }
        if (t == 0) {
            int acc = 0;
            for (int b = 0; b < B_; b++) {
                g_b2s[b] = acc;
                for (int j = 0; j < nsent[b]; j++)
                    if (acc + j < S_) g_s2b[acc + j] = b;
                acc += nsent[b];
            }
            int mi = 0;
            for (int ss = 0; ss < S_; ss++)
                for (int j = 0; j < ntarg[ss]; j++)
                    if (mi < M_) g_m2s[mi++] = ss;
        }
    }

    float v = sf[s * C_ + t];
    float x = v * v;
#pragma unroll
    for (int o = 16; o; o >>= 1) x += __shfl_down_sync(0xffffffffu, x, o);
    __shared__ float red[8];
    if ((t & 31) == 0) red[t >> 5] = x;
    __syncthreads();
    if (t == 0) {
        float acc = 0.f;
#pragma unroll
        for (int i = 0; i < 8; i++) acc += red[i];
        red[0] = acc;
    }
    __syncthreads();
    float n = fmaxf(sqrtf(red[0]), 1e-12f);
    g_sfn[s * C_ + t] = v / n;
}

// ---------------------------------------------------------------------------
// Kernel 2: per-moment top-1 proposal + inter-video loss (128 blocks x 256)
// ---------------------------------------------------------------------------
__global__ void video_kernel(const float* __restrict__ video,
                             const float* __restrict__ iou2ds) {
    int m = blockIdx.x;
    int t = threadIdx.x;
    int sm = g_m2s[m];

    // argmax over P of iou2ds[m, midx[p]] (tie -> lowest p)
    float best = -1e30f;
    int bi = 0;
    for (int p = t; p < P_; p += 256) {
        float v = iou2ds[m * NN_ + g_midx[p]];
        if (v > best) { best = v; bi = p; }
    }
    __shared__ float sv[256];
    __shared__ int   sidx[256];
    sv[t] = best; sidx[t] = bi;
    __syncthreads();
    for (int o = 128; o; o >>= 1) {
        if (t < o) {
            float vo = sv[t + o]; int io = sidx[t + o];
            if (vo > sv[t] || (vo == sv[t] && io < sidx[t])) { sv[t] = vo; sidx[t] = io; }
        }
        __syncthreads();
    }
    int pflat = g_midx[sidx[0]];
    __syncthreads();

    // load v[c], normalize
    float vc = video[((size_t)sm * C_ + t) * NN_ + pflat];
    float x = vc * vc;
#pragma unroll
    for (int o = 16; o; o >>= 1) x += __shfl_down_sync(0xffffffffu, x, o);
    __shared__ float red[8];
    if ((t & 31) == 0) red[t >> 5] = x;
    __syncthreads();
    if (t == 0) {
        float acc = 0.f;
#pragma unroll
        for (int i = 0; i < 8; i++) acc += red[i];
        red[0] = acc;
    }
    __syncthreads();
    float nrm = fmaxf(sqrtf(red[0]), 1e-12f);
    sv[t] = vc / nrm;
    __syncthreads();

    // dots against all 64 normalized sentence vectors
    __shared__ float alls[S_];
    int w = t >> 5, l = t & 31;
#pragma unroll
    for (int k = 0; k < 8; k++) {
        int s = w * 8 + k;
        float acc = 0.f;
#pragma unroll
        for (int c = l; c < C_; c += 32) acc += sv[c] * g_sfn[s * C_ + c];
#pragma unroll
        for (int o = 16; o; o >>= 1) acc += __shfl_down_sync(0xffffffffu, acc, o);
        if (l == 0) alls[s] = acc;
    }
    __syncthreads();
    if (t == 0) {
        float pl = alls[sm] * TINV;
        float neg = 0.f;
        for (int s = 0; s < S_; s++)
            if (s != sm) neg += expf(alls[s] * TINV);
        g_pl[m] = pl;
        g_lossv[m] = logf(expf(pl) + neg) - pl;
    }
}

// ---------------------------------------------------------------------------
// Kernel 3: inter-query fused GEMM + masked exp-sum, full C in-kernel
// grid (PTILES, B), 256 threads; 64s x 128p tile, 4s x 8p micro-tile
// pi = tid&15 (p = pi*8+j), si = tid>>4 (s = si*4+a)
// cp.async double-buffered K pipeline (CK=16 per stage, 16 stages)
// ---------------------------------------------------------------------------
__global__ __launch_bounds__(256, 2) void query_kernel(const float* __restrict__ video,
                                                       const float* __restrict__ iou2d) {
    int pt = blockIdx.x;
    int b  = blockIdx.y;
    int sb = g_b2s[b];
    int tid = threadIdx.x;
    int pi = tid & 15;
    int si = tid >> 4;

    __shared__ float sfc[2][CK * S_];   // [stage][cc*64+s]   8KB
    __shared__ float vt[2][CK][TP];     // [stage][cc][p]    16KB
    __shared__ float pnorm[TP];         //                  0.5KB
    __shared__ float part[S_][16];      //                    4KB

    int ptbase = pt * TP;
    int pcol_l = tid & 127;             // loader's p column
    int ih = tid >> 7;                  // loader's chunk half (0/1)
    int pc = ptbase + pcol_l;
    int fidx = g_midx[pc < P_ ? pc : (P_ - 1)];
    const float* vbase = video + (size_t)sb * C_ * NN_;

    float acc[4][8];
    float accn[8];
#pragma unroll
    for (int a = 0; a < 4; a++)
#pragma unroll
        for (int j = 0; j < 8; j++) acc[a][j] = 0.f;
#pragma unroll
    for (int j = 0; j < 8; j++) accn[j] = 0.f;

    auto load_stage = [&](int chunk, int st) {
        int cb = chunk * CK;
#pragma unroll
        for (int i2 = 0; i2 < 8; i2++) {
            int i = ih * 8 + i2;
            cpa4(&vt[st][i][pcol_l], vbase + (size_t)(cb + i) * NN_ + fidx);
        }
#pragma unroll
        for (int k = 0; k < (CK * S_) / 256; k++) {
            int idx = tid + k * 256;
            int i = idx >> 6, s = idx & 63;
            cpa4(&sfc[st][idx], &g_sfn[s * C_ + cb + i]);
        }
        cpa_commit();
    };

    load_stage(0, 0);
    load_stage(1, 1);

    for (int k = 0; k < CHUNKS; k++) {
        if (k < CHUNKS - 1) cpa_wait1(); else cpa_wait0();
        __syncthreads();
        int st = k & 1;
#pragma unroll
        for (int i = 0; i < CK; i++) {
            float4 v0 = *(const float4*)&vt[st][i][pi * 8];
            float4 v1 = *(const float4*)&vt[st][i][pi * 8 + 4];
            float4 s0 = *(const float4*)&sfc[st][i * 64 + si * 4];
            float vv[8] = {v0.x, v0.y, v0.z, v0.w, v1.x, v1.y, v1.z, v1.w};
            float ss[4] = {s0.x, s0.y, s0.z, s0.w};
            if (si == 0) {
#pragma unroll
                for (int j = 0; j < 8; j++) accn[j] = fmaf(vv[j], vv[j], accn[j]);
            }
#pragma unroll
            for (int a = 0; a < 4; a++)
#pragma unroll
                for (int j = 0; j < 8; j++)
                    acc[a][j] = fmaf(ss[a], vv[j], acc[a][j]);
        }
        __syncthreads();
        if (k + 2 < CHUNKS) load_stage(k + 2, st);
    }

    // broadcast per-p norms (held by si==0 threads)
    if (si == 0) {
#pragma unroll
        for (int j = 0; j < 8; j++) pnorm[pi * 8 + j] = accn[j];
    }
    __syncthreads();

    float inv[8];
#pragma unroll
    for (int j = 0; j < 8; j++)
        inv[j] = TINV / fmaxf(sqrtf(pnorm[pi * 8 + j]), 1e-12f);

    // masked exp-sum per s over this block's 128 p columns
#pragma unroll
    for (int a = 0; a < 4; a++) {
        int s = si * 4 + a;
        bool samevid = (g_s2b[s] == b);
        float sum = 0.f;
#pragma unroll
        for (int j = 0; j < 8; j++) {
            int p = ptbase + pi * 8 + j;
            if (p < P_) {
                bool excl = false;
                if (samevid) {
                    float io = iou2d[s * NN_ + g_midx[p]];
                    excl = (io > NEGIOU);
                }
                if (!excl) sum += __expf(acc[a][j] * inv[j]);
            }
        }
        // accumulate 16 pi-groups per s via two-step: write then reduce
        part[s][pi] = sum;
    }
    __syncthreads();
    if (tid < S_) {
        float tot = 0.f;
#pragma unroll
        for (int kk = 0; kk < 16; kk++) tot += part[tid][kk];
        g_qpart[(b * PTILES + pt) * S_ + tid] = tot;
    }
}

// ---------------------------------------------------------------------------
// Kernel 4: fused qreduce + per-moment losses -> mean  (1 block x 128)
// ---------------------------------------------------------------------------
__global__ void final_kernel(float* __restrict__ out) {
    int t = threadIdx.x;
    __shared__ float qn[2][S_];
    {
        int s = t & 63;
        int h = t >> 6;       // 0 or 1
        float acc = 0.f;
        for (int i = h * 136; i < (h + 1) * 136; i++)
            acc += g_qpart[i * S_ + s];
        qn[h][s] = acc;
    }
    __syncthreads();

    int sm = g_m2s[t];
    float pl = g_pl[t];
    float qneg = qn[0][sm] + qn[1][sm];
    float lq = logf(expf(pl) + qneg) - pl;
    float v = g_lossv[t] + lq;
#pragma unroll
    for (int o = 16; o; o >>= 1) v += __shfl_down_sync(0xffffffffu, v, o);
    __shared__ float red[4];
    if ((t & 31) == 0) red[t >> 5] = v;
    __syncthreads();
    if (t == 0)
        out[0] = (red[0] + red[1] + red[2] + red[3]) / (float)M_;
}

// ---------------------------------------------------------------------------
extern "C" void kernel_launch(void* const* d_in, const int* in_sizes, int n_in,
                              void* d_out, int out_size) {
    const float* video = (const float*)d_in[0];         // (S,C,N,N)
    const float* sents = (const float*)d_in[1];         // (S,C)
    const float* iou2d = (const float*)d_in[2];         // (S,N,N)
    const float* iou2ds = (const float*)d_in[3];        // (M,N,N)
    const int* nsent = (const int*)d_in[4];             // (B,)
    const int* ntarg = (const int*)d_in[5];             // (S,)
    float* out = (float*)d_out;

    sfnorm_setup_kernel<<<S_, 256>>>(sents, nsent, ntarg);
    video_kernel<<<M_, 256>>>(video, iou2ds);
    query_kernel<<<dim3(PTILES, B_), 256>>>(video, iou2d);
    final_kernel<<<1, M_>>>(out);
}

// round 6
// speedup vs baseline: 1.8926x; 1.8580x over previous
#include <cuda_runtime.h>
#include <math.h>
#include <stdint.h>

#define S_ 64
#define C_ 256
#define NN_ 4096
#define B_ 16
#define M_ 128
#define P_ 2080
#define TINV 10.0f
#define NEGIOU 0.5f
#define TP 64
#define PTILES 33           // 33*64 = 2112 >= 2080
#define CK 16
#define CHUNKS (C_/CK)      // 16
#define QB (PTILES*B_)      // 528 query blocks
#define GRID (QB + M_)      // + 128 video blocks

// scratch (device globals; no allocation allowed)
__device__ int   g_midx[P_];
__device__ int   g_b2s[B_];
__device__ int   g_m2s[M_];
__device__ int   g_s2b[S_];
__device__ float g_sfn[S_*C_];   // [s][c] row-major (video role)
__device__ float g_sft[C_*S_];   // [c][s] transposed (query role)
__device__ float g_pl[M_];
__device__ float g_lossv[M_];
__device__ float g_qpart[QB*S_];

// ---------------------------------------------------------------------------
// helpers
// ---------------------------------------------------------------------------
__device__ __forceinline__ void cpa4(void* dst, const void* src) {
    uint32_t d = (uint32_t)__cvta_generic_to_shared(dst);
    asm volatile("cp.async.ca.shared.global [%0], [%1], 4;" :: "r"(d), "l"(src));
}
__device__ __forceinline__ void cpa16(void* dst, const void* src) {
    uint32_t d = (uint32_t)__cvta_generic_to_shared(dst);
    asm volatile("cp.async.cg.shared.global [%0], [%1], 16;" :: "r"(d), "l"(src));
}
__device__ __forceinline__ void cpa_commit() { asm volatile("cp.async.commit_group;"); }
__device__ __forceinline__ void cpa_wait1()  { asm volatile("cp.async.wait_group 1;"); }
__device__ __forceinline__ void cpa_wait0()  { asm volatile("cp.async.wait_group 0;"); }

__device__ __forceinline__ uint64_t packdup(float x) {
    uint64_t r; asm("mov.b64 %0, {%1, %1};" : "=l"(r) : "f"(x)); return r;
}
__device__ __forceinline__ uint64_t fma2(uint64_t a, uint64_t b, uint64_t c) {
    uint64_t d; asm("fma.rn.f32x2 %0, %1, %2, %3;" : "=l"(d) : "l"(a), "l"(b), "l"(c));
    return d;
}
__device__ __forceinline__ void unpack2(uint64_t v, float& lo, float& hi) {
    asm("mov.b64 {%0, %1}, %2;" : "=f"(lo), "=f"(hi) : "l"(v));
}

// ---------------------------------------------------------------------------
// Kernel 1: sf normalize (64 blocks x 256) + transposed copy + setup (blk 0)
// mask2d is static config: triu(64x64), P=2080, generated analytically.
// ---------------------------------------------------------------------------
__global__ void sfnorm_setup_kernel(const float* __restrict__ sf,
                                    const int* __restrict__ nsent,
                                    const int* __restrict__ ntarg) {
    int s = blockIdx.x;
    int t = threadIdx.x; // == c

    if (s == 0) {
        if (t < 64) {
            int off = t * 64 - (t * (t - 1)) / 2;
            for (int c = t; c < 64; c++)
                g_midx[off + (c - t)] = t * 64 + c;
        }
        if (t == 0) {
            int acc = 0;
            for (int b = 0; b < B_; b++) {
                g_b2s[b] = acc;
                for (int j = 0; j < nsent[b]; j++)
                    if (acc + j < S_) g_s2b[acc + j] = b;
                acc += nsent[b];
            }
            int mi = 0;
            for (int ss = 0; ss < S_; ss++)
                for (int j = 0; j < ntarg[ss]; j++)
                    if (mi < M_) g_m2s[mi++] = ss;
        }
    }

    float v = sf[s * C_ + t];
    float x = v * v;
#pragma unroll
    for (int o = 16; o; o >>= 1) x += __shfl_down_sync(0xffffffffu, x, o);
    __shared__ float red[8];
    if ((t & 31) == 0) red[t >> 5] = x;
    __syncthreads();
    if (t == 0) {
        float acc = 0.f;
#pragma unroll
        for (int i = 0; i < 8; i++) acc += red[i];
        red[0] = acc;
    }
    __syncthreads();
    float n = fmaxf(sqrtf(red[0]), 1e-12f);
    float nv = v / n;
    g_sfn[s * C_ + t] = nv;
    g_sft[t * S_ + s] = nv;
}

// ---------------------------------------------------------------------------
// Kernel 2 (mega): blocks [0,QB): inter-query; blocks [QB,QB+M): inter-video
// 128 threads per block.
// ---------------------------------------------------------------------------
__global__ __launch_bounds__(128, 4) void mega_kernel(const float* __restrict__ video,
                                                      const float* __restrict__ iou2d,
                                                      const float* __restrict__ iou2ds) {
    __shared__ __align__(16) char smem_raw[20480];
    int bid = blockIdx.x;
    int tid = threadIdx.x;

    if (bid < QB) {
        // ================= QUERY ROLE =================
        // 64s x 64p tile; micro-tile: 8s (as 4 packed s-pairs) x 4p per thread
        float* vt  = (float*)smem_raw;                 // [2][CK][TP]  8KB
        float* sfc = (float*)(smem_raw + 8192);        // [2][CK*64]   8KB
        float* part = (float*)(smem_raw + 16384);      // [64][16]     4KB

        int b  = bid / PTILES;
        int pt = bid - b * PTILES;
        int sb = g_b2s[b];
        int pi = tid & 15;     // p-group: p = ptbase + pi*4 + j
        int si = tid >> 4;     // s-group: s = si*8 + 2a + h

        int ptbase = pt * TP;
        int pcol_l = tid & 63; // loader's p column
        int ih = tid >> 6;     // loader's c-half
        int pc = ptbase + pcol_l;
        int fidx = g_midx[pc < P_ ? pc : (P_ - 1)];
        const float* vbase = video + (size_t)sb * C_ * NN_;

        uint64_t acc2[4][4];   // [a(s-pair)][j(p)]
        uint64_t accn2[4];
#pragma unroll
        for (int a = 0; a < 4; a++)
#pragma unroll
            for (int j = 0; j < 4; j++) acc2[a][j] = 0ull;
#pragma unroll
        for (int j = 0; j < 4; j++) accn2[j] = 0ull;

        auto load_stage = [&](int chunk, int st) {
            int cb = chunk * CK;
            float* vdst = vt + st * CK * TP;
            float* sdst = sfc + st * CK * S_;
#pragma unroll
            for (int i2 = 0; i2 < 8; i2++) {
                int i = ih * 8 + i2;
                cpa4(&vdst[i * TP + pcol_l], vbase + (size_t)(cb + i) * NN_ + fidx);
            }
            // contiguous 4KB of transposed sf
            const float* ssrc = g_sft + cb * S_;
#pragma unroll
            for (int k = 0; k < 2; k++) {
                int u = tid + k * 128;       // 16B unit index (256 units)
                cpa16(&sdst[u * 4], &ssrc[u * 4]);
            }
            cpa_commit();
        };

        load_stage(0, 0);
        load_stage(1, 1);

        for (int k = 0; k < CHUNKS; k++) {
            if (k < CHUNKS - 1) cpa_wait1(); else cpa_wait0();
            __syncthreads();
            int st = k & 1;
            const float* vrow = vt + st * CK * TP;
            const float* srow = sfc + st * CK * S_;
#pragma unroll
            for (int i = 0; i < CK; i++) {
                float4 vld = *(const float4*)&vrow[i * TP + pi * 4];
                const ulonglong2* sp = (const ulonglong2*)&srow[i * S_ + si * 8];
                ulonglong2 s01 = sp[0];   // packed {s0,s1},{s2,s3}
                ulonglong2 s23 = sp[1];   // packed {s4,s5},{s6,s7}
                uint64_t vp[4];
                vp[0] = packdup(vld.x); vp[1] = packdup(vld.y);
                vp[2] = packdup(vld.z); vp[3] = packdup(vld.w);
                // norms (dup pairs, branch-free; both halves identical)
                accn2[0] = fma2(vp[0], vp[0], accn2[0]);
                accn2[1] = fma2(vp[1], vp[1], accn2[1]);
                accn2[2] = fma2(vp[2], vp[2], accn2[2]);
                accn2[3] = fma2(vp[3], vp[3], accn2[3]);
                uint64_t ss[4] = { s01.x, s01.y, s23.x, s23.y };
#pragma unroll
                for (int a = 0; a < 4; a++)
#pragma unroll
                    for (int j = 0; j < 4; j++)
                        acc2[a][j] = fma2(ss[a], vp[j], acc2[a][j]);
            }
            __syncthreads();
            if (k + 2 < CHUNKS) load_stage(k + 2, k & 1);
        }

        // epilogue
        float inv[4];
#pragma unroll
        for (int j = 0; j < 4; j++) {
            float nlo, nhi;
            unpack2(accn2[j], nlo, nhi);
            inv[j] = TINV / fmaxf(sqrtf(nlo), 1e-12f);
        }

#pragma unroll
        for (int a = 0; a < 4; a++) {
            float dlo[4], dhi[4];
#pragma unroll
            for (int j = 0; j < 4; j++) unpack2(acc2[a][j], dlo[j], dhi[j]);
#pragma unroll
            for (int h = 0; h < 2; h++) {
                int s = si * 8 + 2 * a + h;
                const float* dv = h ? dhi : dlo;
                bool samevid = (g_s2b[s] == b);
                float sum = 0.f;
#pragma unroll
                for (int j = 0; j < 4; j++) {
                    int p = ptbase + pi * 4 + j;
                    if (p < P_) {
                        bool excl = false;
                        if (samevid) {
                            float io = iou2d[s * NN_ + g_midx[p]];
                            excl = (io > NEGIOU);
                        }
                        if (!excl) sum += __expf(dv[j] * inv[j]);
                    }
                }
                part[s * 16 + pi] = sum;
            }
        }
        __syncthreads();
        if (tid < S_) {
            float tot = 0.f;
#pragma unroll
            for (int kk = 0; kk < 16; kk++) tot += part[tid * 16 + kk];
            g_qpart[bid * S_ + tid] = tot;
        }
    } else {
        // ================= VIDEO ROLE =================
        int m = bid - QB;
        int sm = g_m2s[m];
        float* sv   = (float*)smem_raw;                  // [128]
        int*   sidx = (int*)(smem_raw + 512);            // [128]
        float* sv2  = (float*)(smem_raw + 1024);         // [256] normalized v
        float* alls = (float*)(smem_raw + 2048);         // [64]
        float* red  = (float*)(smem_raw + 2304);         // [4]

        // argmax over P of iou2ds[m, midx[p]] (tie -> lowest p)
        float best = -1e30f;
        int bi = 0;
        for (int p = tid; p < P_; p += 128) {
            float v = iou2ds[m * NN_ + g_midx[p]];
            if (v > best) { best = v; bi = p; }
        }
        sv[tid] = best; sidx[tid] = bi;
        __syncthreads();
        for (int o = 64; o; o >>= 1) {
            if (tid < o) {
                float vo = sv[tid + o]; int io = sidx[tid + o];
                if (vo > sv[tid] || (vo == sv[tid] && io < sidx[tid])) {
                    sv[tid] = vo; sidx[tid] = io;
                }
            }
            __syncthreads();
        }
        int pflat = g_midx[sidx[0]];
        __syncthreads();

        // load 2 channels per thread, compute norm
        float vc0 = video[((size_t)sm * C_ + tid) * NN_ + pflat];
        float vc1 = video[((size_t)sm * C_ + tid + 128) * NN_ + pflat];
        float x = vc0 * vc0 + vc1 * vc1;
#pragma unroll
        for (int o = 16; o; o >>= 1) x += __shfl_down_sync(0xffffffffu, x, o);
        if ((tid & 31) == 0) red[tid >> 5] = x;
        __syncthreads();
        float nrm = fmaxf(sqrtf(red[0] + red[1] + red[2] + red[3]), 1e-12f);
        sv2[tid] = vc0 / nrm;
        sv2[tid + 128] = vc1 / nrm;
        __syncthreads();

        // dots against all 64 normalized sentence vectors
        int w = tid >> 5, l = tid & 31;
#pragma unroll
        for (int k = 0; k < 16; k++) {
            int s = w * 16 + k;
            float acc = 0.f;
#pragma unroll
            for (int c = l; c < C_; c += 32) acc += sv2[c] * g_sfn[s * C_ + c];
#pragma unroll
            for (int o = 16; o; o >>= 1) acc += __shfl_down_sync(0xffffffffu, acc, o);
            if (l == 0) alls[s] = acc;
        }
        __syncthreads();
        if (tid == 0) {
            float pl = alls[sm] * TINV;
            float neg = 0.f;
            for (int s = 0; s < S_; s++)
                if (s != sm) neg += expf(alls[s] * TINV);
            g_pl[m] = pl;
            g_lossv[m] = logf(expf(pl) + neg) - pl;
        }
    }
}

// ---------------------------------------------------------------------------
// Kernel 3: qpart reduce + per-moment losses -> mean  (1 block x 512)
// ---------------------------------------------------------------------------
__global__ void final_kernel(float* __restrict__ out) {
    int t = threadIdx.x;
    __shared__ float qn[8][S_];
    __shared__ float qq[S_];
    __shared__ float red[16];
    {
        int s = t & 63;
        int seg = t >> 6;            // 0..7, 528 = 8*66
        float acc = 0.f;
        for (int i = seg * 66; i < seg * 66 + 66; i++)
            acc += g_qpart[i * S_ + s];
        qn[seg][s] = acc;
    }
    __syncthreads();
    if (t < S_) {
        float x = 0.f;
#pragma unroll
        for (int k = 0; k < 8; k++) x += qn[k][t];
        qq[t] = x;
    }
    __syncthreads();

    float v = 0.f;
    if (t < M_) {
        int sm = g_m2s[t];
        float pl = g_pl[t];
        float lq = logf(expf(pl) + qq[sm]) - pl;
        v = g_lossv[t] + lq;
    }
#pragma unroll
    for (int o = 16; o; o >>= 1) v += __shfl_down_sync(0xffffffffu, v, o);
    if ((t & 31) == 0) red[t >> 5] = v;
    __syncthreads();
    if (t == 0) {
        float acc = 0.f;
#pragma unroll
        for (int i = 0; i < 16; i++) acc += red[i];
        out[0] = acc / (float)M_;
    }
}

// ---------------------------------------------------------------------------
extern "C" void kernel_launch(void* const* d_in, const int* in_sizes, int n_in,
                              void* d_out, int out_size) {
    const float* video = (const float*)d_in[0];         // (S,C,N,N)
    const float* sents = (const float*)d_in[1];         // (S,C)
    const float* iou2d = (const float*)d_in[2];         // (S,N,N)
    const float* iou2ds = (const float*)d_in[3];        // (M,N,N)
    const int* nsent = (const int*)d_in[4];             // (B,)
    const int* ntarg = (const int*)d_in[5];             // (S,)
    float* out = (float*)d_out;

    sfnorm_setup_kernel<<<S_, 256>>>(sents, nsent, ntarg);
    mega_kernel<<<GRID, 128>>>(video, iou2d, iou2ds);
    final_kernel<<<1, 512>>>(out);
}

// round 7
// speedup vs baseline: 2.3608x; 1.2474x over previous
#include <cuda_runtime.h>
#include <math.h>
#include <stdint.h>

#define S_ 64
#define C_ 256
#define NN_ 4096
#define B_ 16
#define M_ 128
#define P_ 2080
#define TINV 10.0f
#define NEGIOU 0.5f
#define TP 64
#define PTILES 33           // 33*64 = 2112 >= 2080
#define CK 16
#define CHUNKS (C_/CK)      // 16
#define QB (PTILES*B_)      // 528 query blocks
#define GRID (QB + M_)      // + 128 video blocks
#define NST 3               // cp.async pipeline depth

// scratch (device globals; no allocation allowed)
__device__ int   g_midx[P_];
__device__ int   g_b2s[B_];
__device__ int   g_m2s[M_];
__device__ int   g_s2b[S_];
__device__ float g_sfn[S_*C_];   // [s][c] row-major (video role)
__device__ float g_sft[C_*S_];   // [c][s] transposed (query role)
__device__ float g_pl[M_];
__device__ float g_lossv[M_];
__device__ float g_qpart[QB*S_];

// ---------------------------------------------------------------------------
// helpers
// ---------------------------------------------------------------------------
__device__ __forceinline__ void cpa4(void* dst, const void* src) {
    uint32_t d = (uint32_t)__cvta_generic_to_shared(dst);
    asm volatile("cp.async.ca.shared.global [%0], [%1], 4;" :: "r"(d), "l"(src));
}
__device__ __forceinline__ void cpa16(void* dst, const void* src) {
    uint32_t d = (uint32_t)__cvta_generic_to_shared(dst);
    asm volatile("cp.async.cg.shared.global [%0], [%1], 16;" :: "r"(d), "l"(src));
}
__device__ __forceinline__ void cpa_commit() { asm volatile("cp.async.commit_group;"); }
__device__ __forceinline__ void cpa_wait(int n) {
    if (n >= 2)      asm volatile("cp.async.wait_group 2;");
    else if (n == 1) asm volatile("cp.async.wait_group 1;");
    else             asm volatile("cp.async.wait_group 0;");
}

__device__ __forceinline__ uint64_t packdup(float x) {
    uint64_t r; asm("mov.b64 %0, {%1, %1};" : "=l"(r) : "f"(x)); return r;
}
__device__ __forceinline__ uint64_t fma2(uint64_t a, uint64_t b, uint64_t c) {
    uint64_t d; asm("fma.rn.f32x2 %0, %1, %2, %3;" : "=l"(d) : "l"(a), "l"(b), "l"(c));
    return d;
}
__device__ __forceinline__ void unpack2(uint64_t v, float& lo, float& hi) {
    asm("mov.b64 {%0, %1}, %2;" : "=f"(lo), "=f"(hi) : "l"(v));
}

// ---------------------------------------------------------------------------
// Kernel 1: sf normalize (64 blocks x 256) + transposed copy.
// Block 0 additionally builds midx (analytic triu) and the scatter maps,
// with all raw counts staged into SHARED first (parallel loads) so the
// serial prefix scans touch only smem/registers.
// ---------------------------------------------------------------------------
__global__ void sfnorm_setup_kernel(const float* __restrict__ sf,
                                    const int* __restrict__ nsent,
                                    const int* __restrict__ ntarg) {
    int s = blockIdx.x;
    int t = threadIdx.x; // == c

    __shared__ int sh_ns[B_], sh_nt[S_], sh_cs[B_], sh_ct[S_];
    __shared__ float red[8];

    if (s == 0) {
        if (t < B_) sh_ns[t] = nsent[t];          // parallel global loads
        if (t < S_) sh_nt[t] = ntarg[t];
    }
    __syncthreads();
    if (s == 0) {
        if (t == 0) {                              // scans on smem only
            int a = 0;
#pragma unroll
            for (int b = 0; b < B_; b++) { sh_cs[b] = a; a += sh_ns[b]; }
            int a2 = 0;
#pragma unroll
            for (int q = 0; q < S_; q++) { sh_ct[q] = a2; a2 += sh_nt[q]; }
        }
        if (t < 64) {                              // analytic triu indices
            int off = t * 64 - (t * (t - 1)) / 2;
            for (int c = t; c < 64; c++)
                g_midx[off + (c - t)] = t * 64 + c;
        }
    }
    __syncthreads();
    if (s == 0) {
        if (t < B_) {
            int st = sh_cs[t];
            g_b2s[t] = st;
            for (int j = 0; j < sh_ns[t]; j++)
                if (st + j < S_) g_s2b[st + j] = t;
        }
        if (t < S_) {
            int st = sh_ct[t];
            for (int j = 0; j < sh_nt[t]; j++)
                if (st + j < M_) g_m2s[st + j] = t;
        }
    }

    float v = sf[s * C_ + t];
    float x = v * v;
#pragma unroll
    for (int o = 16; o; o >>= 1) x += __shfl_down_sync(0xffffffffu, x, o);
    if ((t & 31) == 0) red[t >> 5] = x;
    __syncthreads();
    if (t == 0) {
        float acc = 0.f;
#pragma unroll
        for (int i = 0; i < 8; i++) acc += red[i];
        red[0] = acc;
    }
    __syncthreads();
    float n = fmaxf(sqrtf(red[0]), 1e-12f);
    float nv = v / n;
    g_sfn[s * C_ + t] = nv;
    g_sft[t * S_ + s] = nv;
}

// ---------------------------------------------------------------------------
// Kernel 2 (mega): blocks [0,QB): inter-query; blocks [QB,QB+M): inter-video
// 128 threads per block. Query: 64s x 64p tile, FMA2 (f32x2) math,
// 3-stage cp.async pipeline.
// ---------------------------------------------------------------------------
__global__ __launch_bounds__(128, 4) void mega_kernel(const float* __restrict__ video,
                                                      const float* __restrict__ iou2d,
                                                      const float* __restrict__ iou2ds) {
    __shared__ __align__(16) char smem_raw[NST*8192 + 4096];
    int bid = blockIdx.x;
    int tid = threadIdx.x;

    if (bid < QB) {
        // ================= QUERY ROLE =================
        float* vt   = (float*)smem_raw;                      // [NST][CK][TP] 12KB
        float* sfc  = (float*)(smem_raw + NST*4096);         // [NST][CK*64]  12KB
        float* part = (float*)(smem_raw + NST*8192);         // [64][16]       4KB

        int b  = bid / PTILES;
        int pt = bid - b * PTILES;
        int sb = g_b2s[b];
        int pi = tid & 15;     // p-group: p = ptbase + pi*4 + j
        int si = tid >> 4;     // s-group: s = si*8 + 2a + h

        int ptbase = pt * TP;
        int pcol_l = tid & 63; // loader's p column
        int ih = tid >> 6;     // loader's c-half
        int pc = ptbase + pcol_l;
        int fidx = g_midx[pc < P_ ? pc : (P_ - 1)];
        const float* vbase = video + (size_t)sb * C_ * NN_;

        uint64_t acc2[4][4];   // [a(s-pair)][j(p)]
        uint64_t accn2[4];
#pragma unroll
        for (int a = 0; a < 4; a++)
#pragma unroll
            for (int j = 0; j < 4; j++) acc2[a][j] = 0ull;
#pragma unroll
        for (int j = 0; j < 4; j++) accn2[j] = 0ull;

        auto load_stage = [&](int chunk, int st) {
            int cb = chunk * CK;
            float* vdst = vt + st * CK * TP;
            float* sdst = sfc + st * CK * S_;
#pragma unroll
            for (int i2 = 0; i2 < 8; i2++) {
                int i = ih * 8 + i2;
                cpa4(&vdst[i * TP + pcol_l], vbase + (size_t)(cb + i) * NN_ + fidx);
            }
            const float* ssrc = g_sft + cb * S_;
#pragma unroll
            for (int k = 0; k < 2; k++) {
                int u = tid + k * 128;       // 16B unit index (256 units)
                cpa16(&sdst[u * 4], &ssrc[u * 4]);
            }
            cpa_commit();
        };

        load_stage(0, 0);
        load_stage(1, 1);
        load_stage(2, 2);

        int st = 0;
        for (int k = 0; k < CHUNKS; k++) {
            cpa_wait(CHUNKS - 1 - k);
            __syncthreads();
            const float* vrow = vt + st * CK * TP;
            const float* srow = sfc + st * CK * S_;
#pragma unroll
            for (int i = 0; i < CK; i++) {
                float4 vld = *(const float4*)&vrow[i * TP + pi * 4];
                const ulonglong2* sp = (const ulonglong2*)&srow[i * S_ + si * 8];
                ulonglong2 s01 = sp[0];
                ulonglong2 s23 = sp[1];
                uint64_t vp[4];
                vp[0] = packdup(vld.x); vp[1] = packdup(vld.y);
                vp[2] = packdup(vld.z); vp[3] = packdup(vld.w);
                accn2[0] = fma2(vp[0], vp[0], accn2[0]);
                accn2[1] = fma2(vp[1], vp[1], accn2[1]);
                accn2[2] = fma2(vp[2], vp[2], accn2[2]);
                accn2[3] = fma2(vp[3], vp[3], accn2[3]);
                uint64_t ss[4] = { s01.x, s01.y, s23.x, s23.y };
#pragma unroll
                for (int a = 0; a < 4; a++)
#pragma unroll
                    for (int j = 0; j < 4; j++)
                        acc2[a][j] = fma2(ss[a], vp[j], acc2[a][j]);
            }
            __syncthreads();
            if (k + NST < CHUNKS) load_stage(k + NST, st);
            st = (st == NST - 1) ? 0 : st + 1;
        }

        // epilogue
        float inv[4];
#pragma unroll
        for (int j = 0; j < 4; j++) {
            float nlo, nhi;
            unpack2(accn2[j], nlo, nhi);
            inv[j] = TINV / fmaxf(sqrtf(nlo), 1e-12f);
        }

#pragma unroll
        for (int a = 0; a < 4; a++) {
            float dlo[4], dhi[4];
#pragma unroll
            for (int j = 0; j < 4; j++) unpack2(acc2[a][j], dlo[j], dhi[j]);
#pragma unroll
            for (int h = 0; h < 2; h++) {
                int s = si * 8 + 2 * a + h;
                const float* dv = h ? dhi : dlo;
                bool samevid = (g_s2b[s] == b);
                float sum = 0.f;
#pragma unroll
                for (int j = 0; j < 4; j++) {
                    int p = ptbase + pi * 4 + j;
                    if (p < P_) {
                        bool excl = false;
                        if (samevid) {
                            float io = iou2d[s * NN_ + g_midx[p]];
                            excl = (io > NEGIOU);
                        }
                        if (!excl) sum += __expf(dv[j] * inv[j]);
                    }
                }
                part[s * 16 + pi] = sum;
            }
        }
        __syncthreads();
        if (tid < S_) {
            float tot = 0.f;
#pragma unroll
            for (int kk = 0; kk < 16; kk++) tot += part[tid * 16 + kk];
            g_qpart[bid * S_ + tid] = tot;
        }
    } else {
        // ================= VIDEO ROLE =================
        int m = bid - QB;
        int sm = g_m2s[m];
        float* sv   = (float*)smem_raw;                  // [128]
        int*   sidx = (int*)(smem_raw + 512);            // [128]
        float* sv2  = (float*)(smem_raw + 1024);         // [256] normalized v
        float* alls = (float*)(smem_raw + 2048);         // [64]
        float* red  = (float*)(smem_raw + 2304);         // [4]

        // argmax over P of iou2ds[m, midx[p]] (tie -> lowest p)
        float best = -1e30f;
        int bi = 0;
        for (int p = tid; p < P_; p += 128) {
            float v = iou2ds[m * NN_ + g_midx[p]];
            if (v > best) { best = v; bi = p; }
        }
        sv[tid] = best; sidx[tid] = bi;
        __syncthreads();
        for (int o = 64; o; o >>= 1) {
            if (tid < o) {
                float vo = sv[tid + o]; int io = sidx[tid + o];
                if (vo > sv[tid] || (vo == sv[tid] && io < sidx[tid])) {
                    sv[tid] = vo; sidx[tid] = io;
                }
            }
            __syncthreads();
        }
        int pflat = g_midx[sidx[0]];
        __syncthreads();

        // load 2 channels per thread, compute norm
        float vc0 = video[((size_t)sm * C_ + tid) * NN_ + pflat];
        float vc1 = video[((size_t)sm * C_ + tid + 128) * NN_ + pflat];
        float x = vc0 * vc0 + vc1 * vc1;
#pragma unroll
        for (int o = 16; o; o >>= 1) x += __shfl_down_sync(0xffffffffu, x, o);
        if ((tid & 31) == 0) red[tid >> 5] = x;
        __syncthreads();
        float nrm = fmaxf(sqrtf(red[0] + red[1] + red[2] + red[3]), 1e-12f);
        sv2[tid] = vc0 / nrm;
        sv2[tid + 128] = vc1 / nrm;
        __syncthreads();

        // dots against all 64 normalized sentence vectors
        int w = tid >> 5, l = tid & 31;
#pragma unroll
        for (int k = 0; k < 16; k++) {
            int s = w * 16 + k;
            float acc = 0.f;
#pragma unroll
            for (int c = l; c < C_; c += 32) acc += sv2[c] * g_sfn[s * C_ + c];
#pragma unroll
            for (int o = 16; o; o >>= 1) acc += __shfl_down_sync(0xffffffffu, acc, o);
            if (l == 0) alls[s] = acc;
        }
        __syncthreads();
        if (tid == 0) {
            float pl = alls[sm] * TINV;
            float neg = 0.f;
            for (int s = 0; s < S_; s++)
                if (s != sm) neg += expf(alls[s] * TINV);
            g_pl[m] = pl;
            g_lossv[m] = logf(expf(pl) + neg) - pl;
        }
    }
}

// ---------------------------------------------------------------------------
// Kernel 3: qpart reduce (coalesced) + per-moment losses -> mean (1 x 1024)
// thread t handles sentence s = t&63, partial rows i = (t>>6) + 16*k
// ---------------------------------------------------------------------------
__global__ void final_kernel(float* __restrict__ out) {
    int t = threadIdx.x;
    __shared__ float qn[16][S_];
    __shared__ float qq[S_];
    __shared__ float red[32];
    {
        int s  = t & 63;
        int i0 = t >> 6;            // 0..15
        float acc = 0.f;
        for (int i = i0; i < QB; i += 16)   // 33 coalesced, independent loads
            acc += g_qpart[i * S_ + s];
        qn[i0][s] = acc;
    }
    __syncthreads();
    if (t < S_) {
        float x = 0.f;
#pragma unroll
        for (int k = 0; k < 16; k++) x += qn[k][t];
        qq[t] = x;
    }
    __syncthreads();

    float v = 0.f;
    if (t < M_) {
        int sm = g_m2s[t];
        float pl = g_pl[t];
        float lq = logf(expf(pl) + qq[sm]) - pl;
        v = g_lossv[t] + lq;
    }
#pragma unroll
    for (int o = 16; o; o >>= 1) v += __shfl_down_sync(0xffffffffu, v, o);
    if ((t & 31) == 0) red[t >> 5] = v;
    __syncthreads();
    if (t == 0) {
        float acc = 0.f;
#pragma unroll
        for (int i = 0; i < 4; i++) acc += red[i];  // only first 4 warps hold m-losses
        out[0] = acc / (float)M_;
    }
}

// ---------------------------------------------------------------------------
extern "C" void kernel_launch(void* const* d_in, const int* in_sizes, int n_in,
                              void* d_out, int out_size) {
    const float* video = (const float*)d_in[0];         // (S,C,N,N)
    const float* sents = (const float*)d_in[1];         // (S,C)
    const float* iou2d = (const float*)d_in[2];         // (S,N,N)
    const float* iou2ds = (const float*)d_in[3];        // (M,N,N)
    const int* nsent = (const int*)d_in[4];             // (B,)
    const int* ntarg = (const int*)d_in[5];             // (S,)
    float* out = (float*)d_out;

    sfnorm_setup_kernel<<<S_, 256>>>(sents, nsent, ntarg);
    mega_kernel<<<GRID, 128>>>(video, iou2d, iou2ds);
    final_kernel<<<1, 1024>>>(out);
}